// round 7
// baseline (speedup 1.0000x reference)
#include <cuda_runtime.h>
#include <cstdint>

// Problem constants
#define NB    1024
#define NTCR  100
#define NFEAT 15
#define NAA   24
#define NCH   14          // total conv output channels
#define NINST (NB*NTCR)   // 102400
#define INST_PER_BLOCK 16 // 4 warps * 4 instances
#define NBLK_CONV (NINST/INST_PER_BLOCK) // 6400
#define NWPACK 1484       // 1470 weights + 14 biases

// ---------------- scratch (static device memory; no allocation) ----------------
__device__ float g_hbuf[NINST * NCH];   // h vectors (per instance)
__device__ float g_sbuf[NINST];         // attention scores
__device__ float g_zbuf[NB * NCH];      // decoder_f output (pre-BN)
__device__ float g_wpack[NWPACK];       // staged conv weights+bias

// Diagnostic: shifts the ncu -s 5 capture window so convKernel lands on the
// profiled launch index (harness emits 2 internal launches first).
__global__ void dummyKernel() {}

// ---------------- prep: pack conv weights into staging buffer ----------------
__global__ void prepKernel(const float* __restrict__ w0, const float* __restrict__ b0,
                           const float* __restrict__ w1, const float* __restrict__ b1,
                           const float* __restrict__ w2, const float* __restrict__ b2,
                           const float* __restrict__ w3, const float* __restrict__ b3,
                           const float* __restrict__ w4, const float* __restrict__ b4,
                           const float* __restrict__ w5, const float* __restrict__ b5) {
    const int chH[14]    = {2,2,2,3,3,3,4,4,4,5,5,6,6,7};
    const int chF[14]    = {0,1,2,0,1,2,0,1,2,0,1,0,1,0};
    const int chConv[14] = {0,0,0,1,1,1,2,2,2,3,3,4,4,5};
    const float* cws[6] = {w0,w1,w2,w3,w4,w5};
    const float* cbs[6] = {b0,b1,b2,b3,b4,b5};
    int idx = blockIdx.x * blockDim.x + threadIdx.x;
    if (idx < 1470) {
        int ch = idx % 14;
        int r  = idx / 14;
        int t  = r % 7;
        int c  = r / 7;
        int h  = chH[ch];
        float w = 0.0f;
        if (t < h) {
            const float* W = cws[chConv[ch]];
            w = W[(chF[ch] * NFEAT + c) * h + t];
        }
        g_wpack[idx] = w;
    } else if (idx < NWPACK) {
        int ch = idx - 1470;
        g_wpack[idx] = cbs[chConv[ch]][chF[ch]];
    }
}

// ---------------- stage 1: conv + relu + maxpool + fc1 + relu + score ----------------
// 4 instances/warp: weight LDS amortized over 4 FFMAs. x in registers
// (coalesced LDG + shuffle taps), no x smem tile.
__global__ void __launch_bounds__(128) convKernel(const float* __restrict__ x,
                                                  const float* __restrict__ fc1w,
                                                  const float* __restrict__ fc1b,
                                                  const float* __restrict__ waw) {
    __shared__ float ws[NWPACK];    // conv weights + biases
    __shared__ float fcw[196];
    __shared__ float fcb[16];
    __shared__ float wav[16];

    int tid  = threadIdx.x;
    int w    = tid >> 5;
    int lane = tid & 31;

    for (int i = tid; i < NWPACK; i += 128) ws[i] = g_wpack[i];
    for (int i = tid; i < 196; i += 128) fcw[i] = fc1w[i];
    if (tid < 16) {
        fcb[tid] = (tid < 14) ? fc1b[tid] : 0.0f;
        wav[tid] = (tid < 14) ? waw[tid]  : 0.0f;
    }
    __syncthreads();

    int instBase = blockIdx.x * INST_PER_BLOCK + w * 4;
    const float* xg0 = x + (size_t)instBase * 360;
    const float* xg1 = xg0 + 360;
    const float* xg2 = xg1 + 360;
    const float* xg3 = xg2 + 360;

    float a0[14], a1[14], a2[14], a3[14];
    #pragma unroll
    for (int ch = 0; ch < 14; ++ch) { a0[ch] = 0.f; a1[ch] = 0.f; a2[ch] = 0.f; a3[ch] = 0.f; }

    constexpr int CS[7] = {0, 0, 3, 6, 9, 11, 13}; // first active channel per tap

    bool act = (lane < 24);
    float nx0 = act ? xg0[lane] : 0.0f;   // prefetch row c=0
    float nx1 = act ? xg1[lane] : 0.0f;
    float nx2 = act ? xg2[lane] : 0.0f;
    float nx3 = act ? xg3[lane] : 0.0f;

    #pragma unroll 1
    for (int c = 0; c < 15; ++c) {
        float xv0 = nx0, xv1 = nx1, xv2 = nx2, xv3 = nx3;
        if (c < 14) {   // prefetch next row (double-buffer in regs)
            int o = (c + 1) * 24 + lane;
            nx0 = act ? xg0[o] : 0.0f;
            nx1 = act ? xg1[o] : 0.0f;
            nx2 = act ? xg2[o] : 0.0f;
            nx3 = act ? xg3[o] : 0.0f;
        }
        const float* wrow = ws + c * 98;
        #pragma unroll
        for (int t = 0; t < 7; ++t) {
            int src = lane + t; src = (src > 31) ? 31 : src;
            float xt0 = __shfl_sync(0xffffffffu, xv0, src);
            float xt1 = __shfl_sync(0xffffffffu, xv1, src);
            float xt2 = __shfl_sync(0xffffffffu, xv2, src);
            float xt3 = __shfl_sync(0xffffffffu, xv3, src);
            #pragma unroll
            for (int ch = CS[t]; ch < 14; ++ch) {
                float wv = wrow[t * 14 + ch];
                a0[ch] = fmaf(wv, xt0, a0[ch]);
                a1[ch] = fmaf(wv, xt1, a1[ch]);
                a2[ch] = fmaf(wv, xt2, a2[ch]);
                a3[ch] = fmaf(wv, xt3, a3[ch]);
            }
        }
    }

    // bias + relu + masked global max over positions (broadcast to all lanes)
    constexpr int chHt[14] = {2,2,2,3,3,3,4,4,4,5,5,6,6,7};
    #pragma unroll
    for (int ch = 0; ch < 14; ++ch) {
        float bb = ws[1470 + ch];
        float v0 = fmaxf(a0[ch] + bb, 0.0f);
        float v1 = fmaxf(a1[ch] + bb, 0.0f);
        float v2 = fmaxf(a2[ch] + bb, 0.0f);
        float v3 = fmaxf(a3[ch] + bb, 0.0f);
        if (lane > 24 - chHt[ch]) { v0 = 0.f; v1 = 0.f; v2 = 0.f; v3 = 0.f; }
        #pragma unroll
        for (int off = 16; off; off >>= 1) {
            v0 = fmaxf(v0, __shfl_xor_sync(0xffffffffu, v0, off));
            v1 = fmaxf(v1, __shfl_xor_sync(0xffffffffu, v1, off));
            v2 = fmaxf(v2, __shfl_xor_sync(0xffffffffu, v2, off));
            v3 = fmaxf(v3, __shfl_xor_sync(0xffffffffu, v3, off));
        }
        a0[ch] = v0; a1[ch] = v1; a2[ch] = v2; a3[ch] = v3;
    }

    // fc1 + relu + attention score. Pass g handles instances 2g+{0,1}:
    // lanes 0-15 -> sub 0, lanes 16-31 -> sub 1; j = lane&15.
    int sub = lane >> 4;
    int j   = lane & 15;
    #pragma unroll
    for (int g = 0; g < 2; ++g) {
        float h = fcb[j]; // 0 for j>=14
        #pragma unroll
        for (int k = 0; k < 14; ++k) {
            float fA = (g == 0) ? a0[k] : a2[k];
            float fB = (g == 0) ? a1[k] : a3[k];
            float fv = sub ? fB : fA;
            float ww = (j < 14) ? fcw[j * 14 + k] : 0.0f;
            h = fmaf(ww, fv, h);
        }
        h = fmaxf(h, 0.0f);
        float p = h * wav[j]; // 0 for j>=14
        #pragma unroll
        for (int off = 1; off < 16; off <<= 1)
            p += __shfl_xor_sync(0xffffffffu, p, off);
        int inst = instBase + 2 * g + sub;
        if (j < 14) g_hbuf[inst * 14 + j] = h;
        if (j == 0) g_sbuf[inst] = p;
    }
}

// ---------------- stage 2: sparsemax + pooled + decoder_f (one block per repertoire) ----------------
__global__ void __launch_bounds__(128) attnKernel(const float* __restrict__ decfw,
                                                  const float* __restrict__ decfb,
                                                  float* __restrict__ out,
                                                  int write_attw) {
    __shared__ float z[100];
    __shared__ float zsrt[100];
    __shared__ float csh[100];
    __shared__ float aw[100];
    __shared__ float hsh[1400];
    __shared__ float pooled[14];
    __shared__ int   ks_sh;

    int b = blockIdx.x;
    int t = threadIdx.x;

    if (t == 0) ks_sh = 1;
    if (t < 100) z[t] = g_sbuf[b * 100 + t];
    for (int i = t; i < 1400; i += 128) hsh[i] = g_hbuf[b * 1400 + i];
    __syncthreads();

    // exact O(n^2) rank sort (descending, stable)
    if (t < 100) {
        float zi = z[t];
        int r = 0;
        for (int j2 = 0; j2 < 100; ++j2) {
            float zj = z[j2];
            r += (int)(zj > zi) | ((int)(zj == zi) & (int)(j2 < t));
        }
        zsrt[r] = zi;
    }
    __syncthreads();

    // parallel cumsum (triangular) + support-size via atomicMax
    if (t < 100) {
        float cs = 0.0f;
        for (int i2 = 0; i2 <= t; ++i2) cs += zsrt[i2];
        csh[t] = cs;
        if (1.0f + (float)(t + 1) * zsrt[t] > cs) atomicMax(&ks_sh, t + 1);
    }
    __syncthreads();

    int   ks  = ks_sh;
    float tau = (csh[ks - 1] - 1.0f) / (float)ks;

    if (t < 100) {
        float a = fmaxf(z[t] - tau, 0.0f);
        aw[t] = a;
        // attw only emitted when the output buffer has room (OOB-safe).
        if (write_attw) out[2048 + b * 100 + t] = a;
    }
    __syncthreads();

    if (t < 14) {
        float acc = 0.0f;
        #pragma unroll 4
        for (int p = 0; p < 100; ++p)
            acc = fmaf(aw[p], hsh[p * 14 + t], acc);
        pooled[t] = acc;
    }
    __syncthreads();

    if (t < 14) {
        float zz = decfb[t];
        #pragma unroll
        for (int k = 0; k < 14; ++k) zz = fmaf(decfw[t * 14 + k], pooled[k], zz);
        g_zbuf[b * 14 + t] = zz;
    }
}

// ---------------- stage 3: batchnorm (batch stats) + relu + decoder_s ----------------
__global__ void __launch_bounds__(1024) bnKernel(const float* __restrict__ bng,
                                                 const float* __restrict__ bnb,
                                                 const float* __restrict__ dsw,
                                                 const float* __restrict__ dsb,
                                                 float* __restrict__ out) {
    __shared__ float ssum[32][14];
    __shared__ float ssq[32][14];
    __shared__ float mu[14];
    __shared__ float sc[14];

    int b    = threadIdx.x;
    int w    = b >> 5;
    int lane = b & 31;

    float zr[14];
    #pragma unroll
    for (int j = 0; j < 14; ++j) zr[j] = g_zbuf[b * 14 + j];

    #pragma unroll
    for (int j = 0; j < 14; ++j) {
        float s = zr[j];
        float q = zr[j] * zr[j];
        #pragma unroll
        for (int off = 16; off; off >>= 1) {
            s += __shfl_xor_sync(0xffffffffu, s, off);
            q += __shfl_xor_sync(0xffffffffu, q, off);
        }
        if (lane == 0) { ssum[w][j] = s; ssq[w][j] = q; }
    }
    __syncthreads();

    if (b < 14) {
        float s = 0.0f, q = 0.0f;
        #pragma unroll
        for (int i = 0; i < 32; ++i) { s += ssum[i][b]; q += ssq[i][b]; }
        float m = s * (1.0f / 1024.0f);
        float v = q * (1.0f / 1024.0f) - m * m;
        mu[b] = m;
        sc[b] = bng[b] * rsqrtf(v + 1e-5f);
    }
    __syncthreads();

    float l0 = dsb[0], l1 = dsb[1];
    #pragma unroll
    for (int j = 0; j < 14; ++j) {
        float zn = fmaxf((zr[j] - mu[j]) * sc[j] + bnb[j], 0.0f);
        l0 = fmaf(dsw[j],      zn, l0);
        l1 = fmaf(dsw[14 + j], zn, l1);
    }
    out[b * 2]     = l0;
    out[b * 2 + 1] = l1;
}

// ---------------- launch ----------------
extern "C" void kernel_launch(void* const* d_in, const int* in_sizes, int n_in,
                              void* d_out, int out_size) {
    static const int MAP_INS[22] = {0,1,2,3,4,5,6,7,8,9,10,11,12,13,14,15,16,17,18,19,20,21};
    //                       x  cw0 cb0 cw1 cb1 cw2 cb2 cw3 cb3 cw4 cb4 cw5 cb5 f1w f1b waw dfw dfb bng bnb dsw dsb
    static const int MAP_AL[22] = {21, 8,  2,  9,  3, 10,  4, 11,  5, 12,  6, 13,  7, 19, 18, 20, 15, 14,  1,  0, 17, 16};

    const int* M = MAP_INS;
    if (n_in >= 22 && in_sizes[0] != NINST * NFEAT * NAA && in_sizes[21] == NINST * NFEAT * NAA) {
        M = MAP_AL;
    }

    const float* x    = (const float*)d_in[M[0]];
    const float* cw0  = (const float*)d_in[M[1]];
    const float* cb0  = (const float*)d_in[M[2]];
    const float* cw1  = (const float*)d_in[M[3]];
    const float* cb1  = (const float*)d_in[M[4]];
    const float* cw2  = (const float*)d_in[M[5]];
    const float* cb2  = (const float*)d_in[M[6]];
    const float* cw3  = (const float*)d_in[M[7]];
    const float* cb3  = (const float*)d_in[M[8]];
    const float* cw4  = (const float*)d_in[M[9]];
    const float* cb4  = (const float*)d_in[M[10]];
    const float* cw5  = (const float*)d_in[M[11]];
    const float* cb5  = (const float*)d_in[M[12]];
    const float* fc1w = (const float*)d_in[M[13]];
    const float* fc1b = (const float*)d_in[M[14]];
    const float* waw  = (const float*)d_in[M[15]];
    const float* dfw  = (const float*)d_in[M[16]];
    const float* dfb  = (const float*)d_in[M[17]];
    const float* bng  = (const float*)d_in[M[18]];
    const float* bnb  = (const float*)d_in[M[19]];
    const float* dsw  = (const float*)d_in[M[20]];
    const float* dsb  = (const float*)d_in[M[21]];
    float* out = (float*)d_out;

    int write_attw = (out_size >= 2048 + NB * NTCR) ? 1 : 0;

    // Two no-op launches: with the harness's 2 internal launches, these put
    // convKernel at ncu's captured launch index (-s 5 -c 1) for diagnostics.
    dummyKernel<<<1, 32>>>();
    dummyKernel<<<1, 32>>>();
    prepKernel<<<6, 256>>>(cw0, cb0, cw1, cb1, cw2, cb2, cw3, cb3, cw4, cb4, cw5, cb5);
    convKernel<<<NBLK_CONV, 128>>>(x, fc1w, fc1b, waw);
    attnKernel<<<NB, 128>>>(dfw, dfb, out, write_attw);
    bnKernel<<<1, 1024>>>(bng, bnb, dsw, dsb, out);
}

// round 9
// speedup vs baseline: 7.1321x; 7.1321x over previous
#include <cuda_runtime.h>
#include <cstdint>

// Problem constants
#define NB    1024
#define NTCR  100
#define NFEAT 15
#define NAA   24
#define NCH   14          // total conv output channels
#define NINST (NB*NTCR)   // 102400
#define INST_PER_BLOCK 8  // 4 warps * 2 instances
#define NBLK_CONV (NINST/INST_PER_BLOCK) // 12800
#define NWPACK 1484       // 1470 weights (layout [c][ch*7+t]) + 14 biases

// ---------------- scratch (static device memory; no allocation) ----------------
__device__ float g_hbuf[NINST * NCH];   // h vectors (per instance)
__device__ float g_sbuf[NINST];         // attention scores
__device__ float g_zbuf[NB * NCH];      // decoder_f output (pre-BN)
__device__ float g_wpack[NWPACK];       // staged conv weights+bias

// Diagnostic: keeps convKernel at ncu's captured launch index (-s 5 -c 1).
__global__ void dummyKernel() {}

// ---------------- prep: pack conv weights, layout [c][ch*7 + t] ----------------
__global__ void prepKernel(const float* __restrict__ w0, const float* __restrict__ b0,
                           const float* __restrict__ w1, const float* __restrict__ b1,
                           const float* __restrict__ w2, const float* __restrict__ b2,
                           const float* __restrict__ w3, const float* __restrict__ b3,
                           const float* __restrict__ w4, const float* __restrict__ b4,
                           const float* __restrict__ w5, const float* __restrict__ b5) {
    const int chH[14]    = {2,2,2,3,3,3,4,4,4,5,5,6,6,7};
    const int chF[14]    = {0,1,2,0,1,2,0,1,2,0,1,0,1,0};
    const int chConv[14] = {0,0,0,1,1,1,2,2,2,3,3,4,4,5};
    const float* cws[6] = {w0,w1,w2,w3,w4,w5};
    const float* cbs[6] = {b0,b1,b2,b3,b4,b5};
    int idx = blockIdx.x * blockDim.x + threadIdx.x;
    if (idx < 1470) {
        int c  = idx / 98;
        int r  = idx - c * 98;
        int ch = r / 7;
        int t  = r - ch * 7;
        int h  = chH[ch];
        float w = 0.0f;
        if (t < h) {
            const float* W = cws[chConv[ch]];
            w = W[(chF[ch] * NFEAT + c) * h + t];
        }
        g_wpack[idx] = w;
    } else if (idx < NWPACK) {
        int ch = idx - 1470;
        g_wpack[idx] = cbs[chConv[ch]][chF[ch]];
    }
}

// ---------------- stage 1: conv + relu + maxpool + fc1 + relu + score ----------------
// L1tex-minimizing layout (R7 ncu: L1=88%, fma=6% -> LSU-bound).
// lane = (sub, channel): lanes 0-13 inst A ch 0-13, lanes 16-29 inst B.
// Positions p=0..23 live in 24 accumulator REGISTERS per thread.
// Per c-row: 7 weight LDS (conflict-free stride-7) + 6 x LDS.128 (2 distinct
// addresses per warp) feeding 147 FFMAs. No shuffles in the hot path.
__global__ void __launch_bounds__(128) convKernel(const float* __restrict__ x,
                                                  const float* __restrict__ fc1w,
                                                  const float* __restrict__ fc1b,
                                                  const float* __restrict__ waw) {
    __shared__ __align__(16) float xsm[4][720]; // [warp][2 inst * 360]
    __shared__ float wsm[1470];                 // [c][ch*7+t]
    __shared__ float wbias[16];
    __shared__ float fcw[224];                  // 16x14, zero padded
    __shared__ float fcb[16];
    __shared__ float wav[16];
    __shared__ float feats[4][2][16];

    int tid  = threadIdx.x;
    int w    = tid >> 5;
    int lane = tid & 31;

    for (int i = tid; i < 1470; i += 128) wsm[i] = g_wpack[i];
    // BUGFIX (R8): strided loop — 128 threads must fill all 224 entries.
    for (int i = tid; i < 224; i += 128) fcw[i] = (i < 196) ? fc1w[i] : 0.0f;
    if (tid < 16) {
        fcb[tid]   = (tid < 14) ? fc1b[tid] : 0.0f;
        wav[tid]   = (tid < 14) ? waw[tid]  : 0.0f;
        wbias[tid] = (tid < 14) ? g_wpack[1470 + tid] : 0.0f;
    }

    int instBase = blockIdx.x * INST_PER_BLOCK + w * 2;

    // Fill this warp's 2-instance x tile (720 contiguous floats, float4 coalesced)
    {
        const float4* xg = (const float4*)(x + (size_t)instBase * 360);
        float4* xd = (float4*)xsm[w];
        for (int i = lane; i < 180; i += 32) xd[i] = xg[i];
    }
    __syncthreads();

    int sub = lane >> 4;
    int ch  = lane & 15;
    int chc = (ch < 14) ? ch : 13;  // idle lanes mirror ch 13 (harmless)

    const float* xbase = xsm[w] + sub * 360;

    float acc[24];
    #pragma unroll
    for (int p = 0; p < 24; ++p) acc[p] = 0.0f;

    #pragma unroll 1
    for (int c = 0; c < 15; ++c) {
        float wt[7];
        const float* wr = wsm + c * 98 + chc * 7;
        #pragma unroll
        for (int t = 0; t < 7; ++t) wt[t] = wr[t];

        const float4* xv = (const float4*)(xbase + c * 24);
        #pragma unroll
        for (int v = 0; v < 6; ++v) {
            float4 q = xv[v];
            float xe[4] = {q.x, q.y, q.z, q.w};
            #pragma unroll
            for (int e = 0; e < 4; ++e) {
                int a = 4 * v + e;
                #pragma unroll
                for (int t = 0; t < 7; ++t) {
                    if (t <= a) acc[a - t] = fmaf(wt[t], xe[e], acc[a - t]);
                }
            }
        }
    }

    // maxpool over valid positions p <= 24-h (pre-ReLU values can be negative,
    // so invalid tail positions are excluded, not zeroed).
    // h per channel via packed nibbles: ch0..7 = 2,2,2,3,3,3,4,4 ; ch8..13 = 4,5,5,6,6,7
    unsigned hn = (ch < 8) ? (0x44333222u >> (4 * ch)) : (0x00766554u >> (4 * (ch - 8)));
    int plimit = 24 - (int)(hn & 15u);   // valid p in [0, plimit]; plimit in [17,22]

    float m = acc[0];
    #pragma unroll
    for (int p = 1; p <= 17; ++p) m = fmaxf(m, acc[p]);
    #pragma unroll
    for (int p = 18; p <= 22; ++p) if (p <= plimit) m = fmaxf(m, acc[p]);
    float feat = fmaxf(m + wbias[ch], 0.0f);

    if (ch < 14) feats[w][sub][ch] = feat;
    __syncwarp();

    // fc1 + relu + attention score: j = lane&15 output dim, per sub half-warp
    int j = ch;
    float h = fcb[j];
    #pragma unroll
    for (int k = 0; k < 14; ++k)
        h = fmaf(fcw[j * 14 + k], feats[w][sub][k], h);
    h = fmaxf(h, 0.0f);
    float p = h * wav[j]; // 0 for j>=14
    #pragma unroll
    for (int off = 1; off < 16; off <<= 1)
        p += __shfl_xor_sync(0xffffffffu, p, off);

    int inst = instBase + sub;
    if (j < 14) g_hbuf[inst * 14 + j] = h;
    if (j == 0) g_sbuf[inst] = p;
}

// ---------------- stage 2: sparsemax + pooled + decoder_f (one block per repertoire) ----------------
__global__ void __launch_bounds__(128) attnKernel(const float* __restrict__ decfw,
                                                  const float* __restrict__ decfb,
                                                  float* __restrict__ out,
                                                  int write_attw) {
    __shared__ float z[100];
    __shared__ float zsrt[100];
    __shared__ float csh[100];
    __shared__ float aw[100];
    __shared__ float hsh[1400];
    __shared__ float pooled[14];
    __shared__ int   ks_sh;

    int b = blockIdx.x;
    int t = threadIdx.x;

    if (t == 0) ks_sh = 1;
    if (t < 100) z[t] = g_sbuf[b * 100 + t];
    for (int i = t; i < 1400; i += 128) hsh[i] = g_hbuf[b * 1400 + i];
    __syncthreads();

    // exact O(n^2) rank sort (descending, stable)
    if (t < 100) {
        float zi = z[t];
        int r = 0;
        for (int j2 = 0; j2 < 100; ++j2) {
            float zj = z[j2];
            r += (int)(zj > zi) | ((int)(zj == zi) & (int)(j2 < t));
        }
        zsrt[r] = zi;
    }
    __syncthreads();

    // parallel cumsum (triangular) + support-size via atomicMax
    if (t < 100) {
        float cs = 0.0f;
        for (int i2 = 0; i2 <= t; ++i2) cs += zsrt[i2];
        csh[t] = cs;
        if (1.0f + (float)(t + 1) * zsrt[t] > cs) atomicMax(&ks_sh, t + 1);
    }
    __syncthreads();

    int   ks  = ks_sh;
    float tau = (csh[ks - 1] - 1.0f) / (float)ks;

    if (t < 100) {
        float a = fmaxf(z[t] - tau, 0.0f);
        aw[t] = a;
        if (write_attw) out[2048 + b * 100 + t] = a;
    }
    __syncthreads();

    if (t < 14) {
        float acc = 0.0f;
        #pragma unroll 4
        for (int p = 0; p < 100; ++p)
            acc = fmaf(aw[p], hsh[p * 14 + t], acc);
        pooled[t] = acc;
    }
    __syncthreads();

    if (t < 14) {
        float zz = decfb[t];
        #pragma unroll
        for (int k = 0; k < 14; ++k) zz = fmaf(decfw[t * 14 + k], pooled[k], zz);
        g_zbuf[b * 14 + t] = zz;
    }
}

// ---------------- stage 3: batchnorm (batch stats) + relu + decoder_s ----------------
__global__ void __launch_bounds__(1024) bnKernel(const float* __restrict__ bng,
                                                 const float* __restrict__ bnb,
                                                 const float* __restrict__ dsw,
                                                 const float* __restrict__ dsb,
                                                 float* __restrict__ out) {
    __shared__ float ssum[32][14];
    __shared__ float ssq[32][14];
    __shared__ float mu[14];
    __shared__ float sc[14];

    int b    = threadIdx.x;
    int w    = b >> 5;
    int lane = b & 31;

    float zr[14];
    #pragma unroll
    for (int j = 0; j < 14; ++j) zr[j] = g_zbuf[b * 14 + j];

    #pragma unroll
    for (int j = 0; j < 14; ++j) {
        float s = zr[j];
        float q = zr[j] * zr[j];
        #pragma unroll
        for (int off = 16; off; off >>= 1) {
            s += __shfl_xor_sync(0xffffffffu, s, off);
            q += __shfl_xor_sync(0xffffffffu, q, off);
        }
        if (lane == 0) { ssum[w][j] = s; ssq[w][j] = q; }
    }
    __syncthreads();

    if (b < 14) {
        float s = 0.0f, q = 0.0f;
        #pragma unroll
        for (int i = 0; i < 32; ++i) { s += ssum[i][b]; q += ssq[i][b]; }
        float m = s * (1.0f / 1024.0f);
        float v = q * (1.0f / 1024.0f) - m * m;
        mu[b] = m;
        sc[b] = bng[b] * rsqrtf(v + 1e-5f);
    }
    __syncthreads();

    float l0 = dsb[0], l1 = dsb[1];
    #pragma unroll
    for (int j = 0; j < 14; ++j) {
        float zn = fmaxf((zr[j] - mu[j]) * sc[j] + bnb[j], 0.0f);
        l0 = fmaf(dsw[j],      zn, l0);
        l1 = fmaf(dsw[14 + j], zn, l1);
    }
    out[b * 2]     = l0;
    out[b * 2 + 1] = l1;
}

// ---------------- launch ----------------
extern "C" void kernel_launch(void* const* d_in, const int* in_sizes, int n_in,
                              void* d_out, int out_size) {
    static const int MAP_INS[22] = {0,1,2,3,4,5,6,7,8,9,10,11,12,13,14,15,16,17,18,19,20,21};
    //                       x  cw0 cb0 cw1 cb1 cw2 cb2 cw3 cb3 cw4 cb4 cw5 cb5 f1w f1b waw dfw dfb bng bnb dsw dsb
    static const int MAP_AL[22] = {21, 8,  2,  9,  3, 10,  4, 11,  5, 12,  6, 13,  7, 19, 18, 20, 15, 14,  1,  0, 17, 16};

    const int* M = MAP_INS;
    if (n_in >= 22 && in_sizes[0] != NINST * NFEAT * NAA && in_sizes[21] == NINST * NFEAT * NAA) {
        M = MAP_AL;
    }

    const float* x    = (const float*)d_in[M[0]];
    const float* cw0  = (const float*)d_in[M[1]];
    const float* cb0  = (const float*)d_in[M[2]];
    const float* cw1  = (const float*)d_in[M[3]];
    const float* cb1  = (const float*)d_in[M[4]];
    const float* cw2  = (const float*)d_in[M[5]];
    const float* cb2  = (const float*)d_in[M[6]];
    const float* cw3  = (const float*)d_in[M[7]];
    const float* cb3  = (const float*)d_in[M[8]];
    const float* cw4  = (const float*)d_in[M[9]];
    const float* cb4  = (const float*)d_in[M[10]];
    const float* cw5  = (const float*)d_in[M[11]];
    const float* cb5  = (const float*)d_in[M[12]];
    const float* fc1w = (const float*)d_in[M[13]];
    const float* fc1b = (const float*)d_in[M[14]];
    const float* waw  = (const float*)d_in[M[15]];
    const float* dfw  = (const float*)d_in[M[16]];
    const float* dfb  = (const float*)d_in[M[17]];
    const float* bng  = (const float*)d_in[M[18]];
    const float* bnb  = (const float*)d_in[M[19]];
    const float* dsw  = (const float*)d_in[M[20]];
    const float* dsb  = (const float*)d_in[M[21]];
    float* out = (float*)d_out;

    int write_attw = (out_size >= 2048 + NB * NTCR) ? 1 : 0;

    dummyKernel<<<1, 32>>>();
    dummyKernel<<<1, 32>>>();
    prepKernel<<<6, 256>>>(cw0, cb0, cw1, cb1, cw2, cb2, cw3, cb3, cw4, cb4, cw5, cb5);
    convKernel<<<NBLK_CONV, 128>>>(x, fc1w, fc1b, waw);
    attnKernel<<<NB, 128>>>(dfw, dfb, out, write_attw);
    bnKernel<<<1, 1024>>>(bng, bnb, dsw, dsb, out);
}